// round 6
// baseline (speedup 1.0000x reference)
#include <cuda_runtime.h>
#include <cuda_fp16.h>
#include <math.h>

// Problem constants
#define BTT     16
#define NM      1024
#define NL      64
#define NKV     1088
#define DIMM    128
#define HEADS   8
#define INNER   2048
#define QSCALE  0.08838834764831845f   // 128^-0.5
#define KVHALF  544

// Static device scratch
static __device__ __half2 g_m2[HEADS * 64 * DIMM];            // M_h, half2 packed k-pairs [h][k2][n]
static __device__ float   g_n [HEADS * DIMM * DIMM];          // N_h = Wv_h@Wo_h (fp32)
static __device__ float   g_po[2 * BTT * HEADS * NL * DIMM];  // un-normalized O halves
static __device__ float2  g_ml2[2 * BTT * HEADS * NL];        // (m, l) per half per row

// fp32 -> tf32 round-to-nearest (final projection)
__device__ __forceinline__ float cf(float x){
    unsigned u; asm("cvt.rna.tf32.f32 %0, %1;" : "=r"(u) : "f"(x));
    return __uint_as_float(u);
}

__device__ __forceinline__ void mma8(float* d, const unsigned* a, const unsigned* b){
    asm volatile("mma.sync.aligned.m16n8k8.row.col.f32.tf32.tf32.f32 "
        "{%0,%1,%2,%3}, {%4,%5,%6,%7}, {%8,%9}, {%0,%1,%2,%3};"
        : "+f"(d[0]), "+f"(d[1]), "+f"(d[2]), "+f"(d[3])
        : "r"(a[0]), "r"(a[1]), "r"(a[2]), "r"(a[3]), "r"(b[0]), "r"(b[1]));
}

__device__ __forceinline__ void mma16(float* d, const unsigned* a, const unsigned* b){
    asm volatile("mma.sync.aligned.m16n8k16.row.col.f32.f16.f16.f32 "
        "{%0,%1,%2,%3}, {%4,%5,%6,%7}, {%8,%9}, {%0,%1,%2,%3};"
        : "+f"(d[0]), "+f"(d[1]), "+f"(d[2]), "+f"(d[3])
        : "r"(a[0]), "r"(a[1]), "r"(a[2]), "r"(a[3]), "r"(b[0]), "r"(b[1]));
}

__device__ __forceinline__ unsigned u32(__half2 h){ return *(unsigned*)&h; }

// row r of concat(tensor[bt], latents[bt])
__device__ __forceinline__ const float* row_ptr(
    const float* __restrict__ tensor, const float* __restrict__ latents, int bt, int r)
{
    return (r < NM) ? tensor  + ((size_t)bt * NM + r)        * DIMM
                    : latents + ((size_t)bt * NL + (r - NM)) * DIMM;
}

// ===========================================================================
// fp16 fragment compute: 8 warps, warp tile 16 x 64 within CTA N=128.
// A2: half2 [k2][72] (k-pairs packed); B2: half2 [k2 local][136].
// One call = one 64-K chunk (4 k16 steps). k2base offsets A only.
// ===========================================================================
__device__ __forceinline__ void frag16(
    const __half2* __restrict__ A2, const __half2* __restrict__ B2,
    float acc[8][4], int wm, int wn, int grp, int qid, int k2base)
{
    #pragma unroll
    for (int kk2 = 0; kk2 < 32; kk2 += 8) {
        unsigned a[4], b[8][2];
        const int pa0 = (k2base + kk2 + qid) * 72 + wm + grp;
        const int pa1 = (k2base + kk2 + qid + 4) * 72 + wm + grp;
        a[0] = u32(A2[pa0]);   a[1] = u32(A2[pa0 + 8]);
        a[2] = u32(A2[pa1]);   a[3] = u32(A2[pa1 + 8]);
        #pragma unroll
        for (int j = 0; j < 8; j++) {
            const int n = wn + 8*j + grp;
            b[j][0] = u32(B2[(kk2 + qid    ) * 136 + n]);
            b[j][1] = u32(B2[(kk2 + qid + 4) * 136 + n]);
        }
        #pragma unroll
        for (int j = 0; j < 8; j++) mma16(acc[j], a, b[j]);
    }
}

// PV variant: A = P2 (half2 [kv2][72]); B = in_h (half [kv][136], natural
// layout) -> kv-adjacent pairs built from two 16-bit loads.
__device__ __forceinline__ void frag16_pv(
    const __half2* __restrict__ P2, const __half* __restrict__ inH,
    float acc[8][4], int wm, int wn, int grp, int qid, int k2base)
{
    #pragma unroll
    for (int kk2 = 0; kk2 < 32; kk2 += 8) {
        unsigned a[4], b[8][2];
        const int pa0 = (k2base + kk2 + qid) * 72 + wm + grp;
        const int pa1 = (k2base + kk2 + qid + 4) * 72 + wm + grp;
        a[0] = u32(P2[pa0]);   a[1] = u32(P2[pa0 + 8]);
        a[2] = u32(P2[pa1]);   a[3] = u32(P2[pa1 + 8]);
        const int k0 = 2 * (kk2 + qid);          // local kv for b0
        #pragma unroll
        for (int j = 0; j < 8; j++) {
            const int n = wn + 8*j + grp;
            b[j][0] = u32(__halves2half2(inH[(k0  )*136 + n], inH[(k0+1)*136 + n]));
            b[j][1] = u32(__halves2half2(inH[(k0+8)*136 + n], inH[(k0+9)*136 + n]));
        }
        #pragma unroll
        for (int j = 0; j < 8; j++) mma16(acc[j], a, b[j]);
    }
}

// ===========================================================================
// k_flash: grid 256 = (bt,h,half). fp16 tensor cores throughout.
// smem (4B words): SXt 9216 | QWt2 4608 | P2 4608 | Bst 4352 | stats 192
// ===========================================================================
#define FLASH_WORDS (9216 + 4608 + 4608 + 4352 + 192)
#define FLASH_SMEM  (FLASH_WORDS * 4)

__global__ void __launch_bounds__(256, 2) k_flash(
    const float* __restrict__ tensor, const float* __restrict__ latents)
{
    extern __shared__ float sm[];
    float*   SXt   = sm;                              // [128 kv][72] fp32 scores
    __half2* QWt2  = (__half2*)(sm + 9216);           // [64 k2][72]
    __half2* P2    = (__half2*)(sm + 9216 + 4608);    // [64 kv2][72] (also lat staging)
    __half2* Bst2  = (__half2*)(sm + 9216 + 9216);    // [32 k2][136]
    __half*  inH   = (__half*)Bst2;                   // [64 kv][136] halves (union)
    float*   m_run = sm + 9216 + 9216 + 4352;
    float*   l_run = m_run + 64;
    float*   rsc   = l_run + 64;

    const int zz = blockIdx.x;
    const int z = zz >> 1, half = zz & 1;
    const int bt = z >> 3, h = z & 7;
    const int kvbase = half * KVHALF;

    const int t = threadIdx.x, warp = t >> 5, lane = t & 31;
    const int grp = lane >> 2, qid = lane & 3;
    const int wm = (warp & 3) * 16, wn = (warp >> 2) * 64;

    if (t < 64) { m_run[t] = -INFINITY; l_run[t] = 0.f; }

    // stage latents[bt] -> P2 area as half2 [k2][72]
    {
        const int r = t >> 2, k0 = (t & 3) * 32;
        const float* Lp = latents + (size_t)bt * NL * DIMM + (size_t)r * DIMM + k0;
        #pragma unroll
        for (int i = 0; i < 8; i++) {
            float4 v = *(const float4*)(Lp + 4*i);
            P2[(k0/2 + 2*i    ) * 72 + r] = __floats2half2_rn(v.x, v.y);
            P2[(k0/2 + 2*i + 1) * 72 + r] = __floats2half2_rn(v.z, v.w);
        }
    }

    // QW = lat @ M_h  (fp16, K=128 -> two 64-K chunks)
    {
        float qacc[8][4];
        #pragma unroll
        for (int j = 0; j < 8; j++)
            #pragma unroll
            for (int i = 0; i < 4; i++) qacc[j][i] = 0.f;

        for (int c2 = 0; c2 < 64; c2 += 32) {      // k2 chunks of 32
            __syncthreads();
            // stage g_m2 rows [c2, c2+32)
            const int kr = t >> 3, nc = (t & 7) * 16;
            const float4* src = (const float4*)(g_m2 + (size_t)h * 8192
                                                + (size_t)(c2 + kr) * 128 + nc);
            #pragma unroll
            for (int i = 0; i < 4; i++)
                *(float4*)&Bst2[kr * 136 + nc + 4*i] = src[i];
            __syncthreads();
            frag16(P2, Bst2, qacc, wm, wn, grp, qid, c2);
        }
        __syncthreads();
        // epilogue -> QWt2 half2 [k2][72]
        #pragma unroll
        for (int j = 0; j < 8; j++) {
            const int c = wn + 8*j + 2*qid;
            QWt2[(c >> 1) * 72 + wm + grp    ] = __floats2half2_rn(qacc[j][0], qacc[j][1]);
            QWt2[(c >> 1) * 72 + wm + grp + 8] = __floats2half2_rn(qacc[j][2], qacc[j][3]);
        }
    }

    float O[8][4];
    #pragma unroll
    for (int j = 0; j < 8; j++)
        #pragma unroll
        for (int i = 0; i < 4; i++) O[j][i] = 0.f;

    for (int kv0 = 0; kv0 < KVHALF; kv0 += 128) {
        const int valid = (KVHALF - kv0 < 128) ? (KVHALF - kv0) : 128;  // 128 or 32

        // ---- S block = QW @ in_blk^T (fp16), K=128 dims in two 64 chunks ----
        float sacc[8][4];
        #pragma unroll
        for (int j = 0; j < 8; j++)
            #pragma unroll
            for (int i = 0; i < 4; i++) sacc[j][i] = 0.f;

        for (int c = 0; c < 128; c += 64) {
            __syncthreads();
            // tb stage: Bst2[k2 local][kv n], dim-adjacent pairs packed
            const int bn = t >> 1, dk = (t & 1) * 32;
            const bool v = bn < valid;
            const float* Bp = row_ptr(tensor, latents, bt,
                                      kvbase + kv0 + (v ? bn : 0)) + c + dk;
            #pragma unroll
            for (int i = 0; i < 8; i++) {
                float4 w = v ? *(const float4*)(Bp + 4*i) : make_float4(0.f,0.f,0.f,0.f);
                Bst2[(dk/2 + 2*i    ) * 136 + bn] = __floats2half2_rn(w.x, w.y);
                Bst2[(dk/2 + 2*i + 1) * 136 + bn] = __floats2half2_rn(w.z, w.w);
            }
            __syncthreads();
            frag16(QWt2, Bst2, sacc, wm, wn, grp, qid, c >> 1);
        }

        // sacc -> SXt (fp32, [kv][row])
        #pragma unroll
        for (int j = 0; j < 8; j++) {
            const int c = wn + 8*j + 2*qid;
            if (c < valid) {
                SXt[(c  )*72 + wm+grp  ] = sacc[j][0];
                SXt[(c  )*72 + wm+grp+8] = sacc[j][2];
            }
            if (c + 1 < valid) {
                SXt[(c+1)*72 + wm+grp  ] = sacc[j][1];
                SXt[(c+1)*72 + wm+grp+8] = sacc[j][3];
            }
        }
        __syncthreads();

        // ---- online softmax (4 threads per row), write P2 half2 ----
        {
            const int row = t >> 2, part = t & 3;
            const float mo = m_run[row];
            float mx = mo;
            #pragma unroll 8
            for (int i = 0; i < 32; i++) {
                const int c = part * 32 + i;
                if (c < valid) mx = fmaxf(mx, SXt[c*72 + row]);
            }
            mx = fmaxf(mx, __shfl_xor_sync(0xffffffffu, mx, 1));
            mx = fmaxf(mx, __shfl_xor_sync(0xffffffffu, mx, 2));
            float s = 0.f;
            #pragma unroll 8
            for (int i = 0; i < 16; i++) {
                const int c0 = part * 32 + 2*i;
                float e0 = 0.f, e1 = 0.f;
                if (c0     < valid) { e0 = __expf(SXt[(c0  )*72 + row] - mx); s += e0; }
                if (c0 + 1 < valid) { e1 = __expf(SXt[(c0+1)*72 + row] - mx); s += e1; }
                P2[(c0 >> 1) * 72 + row] = __floats2half2_rn(e0, e1);
            }
            s += __shfl_xor_sync(0xffffffffu, s, 1);
            s += __shfl_xor_sync(0xffffffffu, s, 2);
            if (part == 0) {
                const float scale = __expf(mo - mx);
                l_run[row] = l_run[row] * scale + s;
                m_run[row] = mx;
                rsc[row]   = scale;
            }
        }
        __syncthreads();

        // ---- rescale O, then O += P @ in_blk (fp16) ----
        {
            const float s0 = rsc[wm+grp], s1 = rsc[wm+grp+8];
            #pragma unroll
            for (int j = 0; j < 8; j++) {
                O[j][0] *= s0; O[j][1] *= s0;
                O[j][2] *= s1; O[j][3] *= s1;
            }
        }
        const int nch = (valid + 63) >> 6;           // 2 or 1 chunks of 64 kv
        for (int cc = 0; cc < nch * 64; cc += 64) {
            __syncthreads();
            // stage in_h [64 kv][136] halves (natural layout)
            const int br = t >> 2, bc = (t & 3) * 32;
            int gr = kvbase + kv0 + cc + br;
            if (gr >= NKV) gr = NKV - 1;             // clamp; P2 is zero there
            const float* Bp = row_ptr(tensor, latents, bt, gr) + bc;
            __half2* dst = (__half2*)(inH + br * 136 + bc);
            #pragma unroll
            for (int i = 0; i < 8; i++) {
                float4 w = *(const float4*)(Bp + 4*i);
                dst[2*i    ] = __floats2half2_rn(w.x, w.y);
                dst[2*i + 1] = __floats2half2_rn(w.z, w.w);
            }
            __syncthreads();
            frag16_pv(P2, inH, O, wm, wn, grp, qid, cc >> 1);
        }
        __syncthreads();
    }

    // store un-normalized O + (m,l)
    if (t < 64) g_ml2[(size_t)zz * NL + t] = make_float2(m_run[t], l_run[t]);
    float* P = g_po + (size_t)zz * NL * DIMM;
    #pragma unroll
    for (int j = 0; j < 8; j++) {
        const int c = wn + 8*j + 2*qid;
        *(float2*)&P[(size_t)(wm+grp  ) * DIMM + c] = make_float2(O[j][0], O[j][1]);
        *(float2*)&P[(size_t)(wm+grp+8) * DIMM + c] = make_float2(O[j][2], O[j][3]);
    }
}

// ===========================================================================
// k_prep: fp32 64x64 cores; M branch packs g_m2 half2, N branch writes g_n.
// ===========================================================================
__global__ void k_prep(const float* __restrict__ Wq, const float* __restrict__ Wkv,
                       const float* __restrict__ Wo)
{
    __shared__ float As[16][68];
    __shared__ float Bs[16][68];
    const int b = blockIdx.x;
    const bool is_m = (b < 32);
    const int idx = is_m ? b : b - 32;
    const int h = idx >> 2, sub = idx & 3;
    const int m0 = (sub >> 1) * 64, n0 = (sub & 1) * 64;

    const int t  = threadIdx.x;
    const int tx = t & 15, ty = t >> 4;
    const int am = t >> 2, ak = (t & 3) << 2;
    float acc[4][4] = {};

    if (is_m) {
        // M_h = QSCALE * Wq_h @ Wk_h^T  (NT, K=256)
        const int bn = t >> 2, bq = (t & 3) << 2;
        const float* Ap = Wq  + h * 256 + (size_t)(m0 + am) * INNER + ak;
        const float* Bp = Wkv + h * 256 + (size_t)(n0 + bn) * (2*INNER) + bq;
        for (int kb = 0; kb < 256; kb += 16) {
            float4 a = *(const float4*)(Ap + kb);
            float4 bb = *(const float4*)(Bp + kb);
            As[ak+0][am] = a.x; As[ak+1][am] = a.y; As[ak+2][am] = a.z; As[ak+3][am] = a.w;
            Bs[bq+0][bn] = bb.x; Bs[bq+1][bn] = bb.y; Bs[bq+2][bn] = bb.z; Bs[bq+3][bn] = bb.w;
            __syncthreads();
            #pragma unroll
            for (int k = 0; k < 16; ++k) {
                float4 av = *(const float4*)&As[k][ty << 2];
                float4 bv = *(const float4*)&Bs[k][tx << 2];
                acc[0][0] += av.x*bv.x; acc[0][1] += av.x*bv.y; acc[0][2] += av.x*bv.z; acc[0][3] += av.x*bv.w;
                acc[1][0] += av.y*bv.x; acc[1][1] += av.y*bv.y; acc[1][2] += av.y*bv.z; acc[1][3] += av.y*bv.w;
                acc[2][0] += av.z*bv.x; acc[2][1] += av.z*bv.y; acc[2][2] += av.z*bv.z; acc[2][3] += av.z*bv.w;
                acc[3][0] += av.w*bv.x; acc[3][1] += av.w*bv.y; acc[3][2] += av.w*bv.z; acc[3][3] += av.w*bv.w;
            }
            __syncthreads();
        }
        // pack rows (r, r+1) into half2 -> g_m2[h][k2][n]
        const int r0 = m0 + (ty << 2), c0 = n0 + (tx << 2);
        #pragma unroll
        for (int cc = 0; cc < 4; cc++) {
            g_m2[(size_t)h*8192 + ((r0>>1)  )*128 + c0+cc] =
                __floats2half2_rn(acc[0][cc]*QSCALE, acc[1][cc]*QSCALE);
            g_m2[(size_t)h*8192 + ((r0>>1)+1)*128 + c0+cc] =
                __floats2half2_rn(acc[2][cc]*QSCALE, acc[3][cc]*QSCALE);
        }
    } else {
        // N_h = Wv_h @ Wo_h  (NN, K=256) -> fp32 g_n
        const int bk = t >> 4, bn = (t & 15) << 2;
        const float* Ap = Wkv + INNER + h * 256 + (size_t)(m0 + am) * (2*INNER) + ak;
        const float* Bp = Wo + (size_t)h * 256 * DIMM + (size_t)bk * DIMM + n0 + bn;
        for (int kb = 0; kb < 256; kb += 16) {
            float4 a = *(const float4*)(Ap + kb);
            float4 bb = *(const float4*)(Bp + (size_t)kb * DIMM);
            As[ak+0][am] = a.x; As[ak+1][am] = a.y; As[ak+2][am] = a.z; As[ak+3][am] = a.w;
            *(float4*)&Bs[bk][bn] = bb;
            __syncthreads();
            #pragma unroll
            for (int k = 0; k < 16; ++k) {
                float4 av = *(const float4*)&As[k][ty << 2];
                float4 bv = *(const float4*)&Bs[k][tx << 2];
                acc[0][0] += av.x*bv.x; acc[0][1] += av.x*bv.y; acc[0][2] += av.x*bv.z; acc[0][3] += av.x*bv.w;
                acc[1][0] += av.y*bv.x; acc[1][1] += av.y*bv.y; acc[1][2] += av.y*bv.z; acc[1][3] += av.y*bv.w;
                acc[2][0] += av.z*bv.x; acc[2][1] += av.z*bv.y; acc[2][2] += av.z*bv.z; acc[2][3] += av.z*bv.w;
                acc[3][0] += av.w*bv.x; acc[3][1] += av.w*bv.y; acc[3][2] += av.w*bv.z; acc[3][3] += av.w*bv.w;
            }
            __syncthreads();
        }
        float* C = g_n + (size_t)h * DIMM * DIMM;
        #pragma unroll
        for (int i = 0; i < 4; ++i) {
            float4 r;
            r.x = acc[i][0]; r.y = acc[i][1]; r.z = acc[i][2]; r.w = acc[i][3];
            *(float4*)&C[(size_t)(m0 + (ty << 2) + i) * DIMM + n0 + (tx << 2)] = r;
        }
    }
}

// ===========================================================================
// k_final: per bt, out = sum_h (combined PI_h) @ N_h as one K=1024 tf32 GEMM.
// Flash-combine (merge two KV halves + 1/l) fused into the A loader.
// ===========================================================================
__global__ void __launch_bounds__(128) k_final(float* __restrict__ out)
{
    __shared__ float As[32][72];
    __shared__ float Bs[32][136];
    const int bt = blockIdx.x;
    const int t    = threadIdx.x;
    const int warp = t >> 5, lane = t & 31;
    const int grp  = lane >> 2, qid = lane & 3;
    const int wm   = (warp & 1) * 32, wn = (warp >> 1) * 64;
    const int arow = t >> 1, ak0 = (t & 1) * 16;
    const int brow = t >> 2, bcol = (t & 3) * 32;

    // per-head combine scalars for row arow
    float e0a[8], e1a[8];
    #pragma unroll
    for (int h = 0; h < 8; h++) {
        const int z = bt * HEADS + h;
        float2 ml0 = g_ml2[(size_t)(z*2  ) * NL + arow];
        float2 ml1 = g_ml2[(size_t)(z*2+1) * NL + arow];
        const float mm = fmaxf(ml0.x, ml1.x);
        const float a0 = __expf(ml0.x - mm), a1 = __expf(ml1.x - mm);
        const float il = 1.0f / (ml0.y * a0 + ml1.y * a1);
        e0a[h] = a0 * il; e1a[h] = a1 * il;
    }

    float acc[2][8][4];
    #pragma unroll
    for (int f = 0; f < 2; f++)
        #pragma unroll
        for (int j = 0; j < 8; j++)
            #pragma unroll
            for (int i = 0; i < 4; i++) acc[f][j][i] = 0.f;

    for (int c = 0; c < 32; c++) {                 // 32 chunks of K=32
        const int h = c >> 2, dk = (c & 3) * 32;
        const int z = bt * HEADS + h;
        const float e0 = e0a[h], e1 = e1a[h];
        const float* O0 = g_po + (size_t)(z*2  ) * NL * DIMM
                         + (size_t)arow * DIMM + dk + ak0;
        const float* O1 = g_po + (size_t)(z*2+1) * NL * DIMM
                         + (size_t)arow * DIMM + dk + ak0;
        const float* Bp = g_n + (size_t)h * DIMM * DIMM
                         + (size_t)(dk + brow) * DIMM + bcol;
        #pragma unroll
        for (int i = 0; i < 4; i++) {
            float4 a = *(const float4*)(O0 + 4*i);
            float4 b = *(const float4*)(O1 + 4*i);
            const int kc = ak0 + 4*i;
            As[kc+0][arow] = cf(e0*a.x + e1*b.x);
            As[kc+1][arow] = cf(e0*a.y + e1*b.y);
            As[kc+2][arow] = cf(e0*a.z + e1*b.z);
            As[kc+3][arow] = cf(e0*a.w + e1*b.w);
        }
        #pragma unroll
        for (int i = 0; i < 8; i++) {
            float4 v = *(const float4*)(Bp + 4*i);
            float4 w;
            w.x = cf(v.x); w.y = cf(v.y); w.z = cf(v.z); w.w = cf(v.w);
            *(float4*)&Bs[brow][bcol + 4*i] = w;
        }
        __syncthreads();
        #pragma unroll
        for (int kk = 0; kk < 32; kk += 8) {
            unsigned a[2][4], b[8][2];
            #pragma unroll
            for (int f = 0; f < 2; f++) {
                a[f][0] = __float_as_uint(As[kk+qid  ][wm+16*f+grp  ]);
                a[f][1] = __float_as_uint(As[kk+qid  ][wm+16*f+grp+8]);
                a[f][2] = __float_as_uint(As[kk+qid+4][wm+16*f+grp  ]);
                a[f][3] = __float_as_uint(As[kk+qid+4][wm+16*f+grp+8]);
            }
            #pragma unroll
            for (int j = 0; j < 8; j++) {
                b[j][0] = __float_as_uint(Bs[kk+qid  ][wn+8*j+grp]);
                b[j][1] = __float_as_uint(Bs[kk+qid+4][wn+8*j+grp]);
            }
            #pragma unroll
            for (int f = 0; f < 2; f++)
                #pragma unroll
                for (int j = 0; j < 8; j++) mma8(acc[f][j], a[f], b[j]);
        }
        __syncthreads();
    }

    float* C = out + (size_t)bt * NL * DIMM;
    #pragma unroll
    for (int f = 0; f < 2; f++) {
        const int r0 = wm + 16*f + grp;
        #pragma unroll
        for (int j = 0; j < 8; j++) {
            const int col = wn + 8*j + 2*qid;
            *(float2*)&C[(size_t)r0 * DIMM + col] = make_float2(acc[f][j][0], acc[f][j][1]);
            *(float2*)&C[(size_t)(r0+8) * DIMM + col] = make_float2(acc[f][j][2], acc[f][j][3]);
        }
    }
}

// ---------------------------------------------------------------------------

extern "C" void kernel_launch(void* const* d_in, const int* in_sizes, int n_in,
                              void* d_out, int out_size)
{
    const float* tensor  = (const float*)d_in[0];
    const float* latents = (const float*)d_in[1];
    const float* Wq      = (const float*)d_in[2];
    const float* Wkv     = (const float*)d_in[3];
    const float* Wo      = (const float*)d_in[4];
    float*       out     = (float*)d_out;

    (void)in_sizes; (void)n_in; (void)out_size;

    cudaFuncSetAttribute(k_flash, cudaFuncAttributeMaxDynamicSharedMemorySize, FLASH_SMEM);

    k_prep <<<64, 256>>>(Wq, Wkv, Wo);
    k_flash<<<2 * BTT * HEADS, 256, FLASH_SMEM>>>(tensor, latents);
    k_final<<<BTT, 128>>>(out);
}